// round 15
// baseline (speedup 1.0000x reference)
#include <cuda_runtime.h>
#include <cuda_fp16.h>
#include <cstdint>

#define BB    64
#define TT    512
#define DIN   512
#define DHID  1024
#define DOUT  512
#define NDAYS 24
#define EPS_  1e-5f

// Scratch (__device__ globals; no runtime allocation).
__device__ __half g_xh [(size_t)BB * TT * DIN];       // 32 MB x -> fp16
__device__ __half g_h  [(size_t)BB * TT * DHID];      // 64 MB hidden fp16
__device__ __half g_wt1[(size_t)NDAYS * DHID * DIN];  // 24 MB W1^T [d][n][k] fp16
__device__ __half g_wt2[(size_t)NDAYS * DOUT * DHID]; // 24 MB W2^T [d][n][k] fp16

// ---------------------------------------------------------------- helpers
__device__ __forceinline__ uint32_t smem_u32(const void* p) {
    uint32_t a;
    asm("{ .reg .u64 t; cvta.to.shared.u64 t, %1; cvt.u32.u64 %0, t; }"
        : "=r"(a) : "l"(p));
    return a;
}
__device__ __forceinline__ void cp16(uint32_t dst, const void* src) {
    asm volatile("cp.async.cg.shared.global [%0], [%1], 16;"
                 :: "r"(dst), "l"(src) : "memory");
}
__device__ __forceinline__ void ldm4(uint32_t& r0, uint32_t& r1,
                                     uint32_t& r2, uint32_t& r3, uint32_t a) {
    asm volatile("ldmatrix.sync.aligned.m8n8.x4.shared.b16 {%0,%1,%2,%3}, [%4];"
                 : "=r"(r0), "=r"(r1), "=r"(r2), "=r"(r3) : "r"(a));
}
__device__ __forceinline__ void mma16816(float* c, const uint32_t* a,
                                         uint32_t b0, uint32_t b1) {
    asm volatile(
        "mma.sync.aligned.m16n8k16.row.col.f32.f16.f16.f32 "
        "{%0,%1,%2,%3}, {%4,%5,%6,%7}, {%8,%9}, {%0,%1,%2,%3};"
        : "+f"(c[0]), "+f"(c[1]), "+f"(c[2]), "+f"(c[3])
        : "r"(a[0]), "r"(a[1]), "r"(a[2]), "r"(a[3]), "r"(b0), "r"(b1));
}

// ---------------------------------------------------------------- W transpose tile
// Transpose 128(k) x 32(n) region of W [NDAYS][K][N] fp32 -> Wt [NDAYS][N][K] fp16.
template<int K, int N>
__device__ __forceinline__ void transpose_tile_wide(const float* __restrict__ W,
                                                    __half* __restrict__ Wt,
                                                    int d, int n0, int k0,
                                                    float (*t)[33], int tid) {
    const float* Wd  = W  + (size_t)d * K * N;
    __half*      Wtd = Wt + (size_t)d * N * K;

    const int kr = tid >> 3;
    const int c  = (tid & 7) * 4;
    float4 v[4];
    #pragma unroll
    for (int g = 0; g < 4; g++)
        v[g] = *(const float4*)(Wd + (size_t)(k0 + g * 32 + kr) * N + n0 + c);
    #pragma unroll
    for (int g = 0; g < 4; g++) {
        const int k = g * 32 + kr;
        t[k][c + 0] = v[g].x; t[k][c + 1] = v[g].y;
        t[k][c + 2] = v[g].z; t[k][c + 3] = v[g].w;
    }
    __syncthreads();

    #pragma unroll
    for (int p = 0; p < 2; p++) {
        const int cix = p * 256 + tid;
        const int n   = cix & 31;
        const int kb  = (cix >> 5) * 8;
        __half2 h[4];
        #pragma unroll
        for (int i = 0; i < 4; i++)
            h[i] = __floats2half2_rn(t[kb + 2 * i][n], t[kb + 2 * i + 1][n]);
        uint4 o;
        o.x = *(uint32_t*)&h[0]; o.y = *(uint32_t*)&h[1];
        o.z = *(uint32_t*)&h[2]; o.w = *(uint32_t*)&h[3];
        *(uint4*)(Wtd + (size_t)(n0 + n) * K + k0 + kb) = o;
    }
}

// ---------------------------------------------------------------- prep1: x + W1
#define NBLK_X  4096                                  // (BB*TT*DIN/16)/256
#define NBLK_W1 ((DHID / 32) * (DIN / 128) * NDAYS)   // 3072
#define NBLK_W2 ((DOUT / 32) * (DHID / 128) * NDAYS)  // 3072

__global__ __launch_bounds__(256) void prep1_kernel(
    const float4* __restrict__ x, uint4* __restrict__ xh,
    const float* __restrict__ W1, __half* __restrict__ wt1)
{
    __shared__ float t[128][33];
    const int blk = blockIdx.x;
    const int tid = threadIdx.x;
    if (blk < NBLK_X) {
        const int i = blk * 256 + tid;
        float4 v[4];
        #pragma unroll
        for (int j = 0; j < 4; j++) v[j] = x[i * 4 + j];
        __half2 h[8];
        #pragma unroll
        for (int j = 0; j < 4; j++) {
            h[j * 2 + 0] = __floats2half2_rn(v[j].x, v[j].y);
            h[j * 2 + 1] = __floats2half2_rn(v[j].z, v[j].w);
        }
        uint4 o0, o1;
        o0.x = *(uint32_t*)&h[0]; o0.y = *(uint32_t*)&h[1];
        o0.z = *(uint32_t*)&h[2]; o0.w = *(uint32_t*)&h[3];
        o1.x = *(uint32_t*)&h[4]; o1.y = *(uint32_t*)&h[5];
        o1.z = *(uint32_t*)&h[6]; o1.w = *(uint32_t*)&h[7];
        xh[i * 2 + 0] = o0;
        xh[i * 2 + 1] = o1;
    } else {
        int r = blk - NBLK_X;
        const int d = r / 128; r %= 128;
        const int n0 = (r % 32) * 32;
        const int k0 = (r / 32) * 128;
        transpose_tile_wide<DIN, DHID>(W1, wt1, d, n0, k0, t, tid);
    }
}

// ---------------------------------------------------------------- FP16 GEMM (= R8/R12)
// 256 threads, 8 warps 2(M) x 4(N); warp tile 64x32; K-chunk 64; 3 stages.
// FUSEW2=true (GEMM1): grid is 5120 linear blocks, groups of 5 = 2 GEMM +
// 3 W2-transpose blocks interleaved so the W2 prep hides in GEMM1's DRAM /
// SM-slot slack. Stream order still makes wt2 ready before GEMM2.
#define STAGES 3
#define STAGE_BYTES 32768
#define SMEM_DYN (STAGES * STAGE_BYTES)

template<int KDIM, int NTOT, bool RELU, bool FUSEW2, typename CT>
__global__ __launch_bounds__(256, 2) void gemm_mma(
    const __half* __restrict__ A,
    const __half* __restrict__ Wt,
    const float*  __restrict__ bias,
    const int*    __restrict__ day,
    CT*           __restrict__ C,
    const float*  __restrict__ W2,    // FUSEW2 only
    __half*       __restrict__ wt2)   // FUSEW2 only
{
    extern __shared__ char smem[];
    const uint32_t sbase = smem_u32(smem);

    const int tid  = threadIdx.x;

    int bb, my, mz;
    if constexpr (FUSEW2) {
        const int g5 = blockIdx.x / 5;
        const int r5 = blockIdx.x % 5;
        if (r5 >= 2) {
            // W2 transpose block: t = g5*3 + (r5-2), 0..3071
            int r = g5 * 3 + (r5 - 2);
            const int d = r / 128; r %= 128;
            const int n0 = (r % 16) * 32;
            const int k0 = (r / 16) * 128;
            transpose_tile_wide<DHID, DOUT>(W2, wt2, d, n0, k0,
                                            (float (*)[33])smem, tid);
            return;
        }
        const int gi = g5 * 2 + r5;         // 0..2047
        bb = gi & 63;
        my = (gi >> 6) & 3;
        mz = gi >> 8;                        // 0..7
    } else {
        bb = blockIdx.x; my = blockIdx.y; mz = blockIdx.z;
    }

    const int lane = tid & 31;
    const int wid  = tid >> 5;
    const int wm   = wid & 1;
    const int wn   = wid >> 1;

    const int b  = bb;
    const int m0 = my * 128;
    const int n0 = mz * 128;
    const int d  = __ldg(day + b);

    const __half* Arow = A  + (size_t)(b * TT + m0) * KDIM;
    const __half* Brow = Wt + ((size_t)d * NTOT + n0) * KDIM;

    const int lrow = tid >> 3;
    const int lchk = tid & 7;

    constexpr int KT = KDIM / 64;

    auto cp_part = [&](int s, int kt, int p) {
        const uint32_t as_ = sbase + s * STAGE_BYTES;
        const int row = p * 32 + lrow;
        const uint32_t soff = row * 128 + ((lchk ^ (row & 7)) << 4);
        const size_t goff = (size_t)kt * 64 + (size_t)row * KDIM + lchk * 8;
        cp16(as_ + soff,         Arow + goff);
        cp16(as_ + 16384 + soff, Brow + goff);
    };
    auto cp_stage = [&](int s, int kt) {
        #pragma unroll
        for (int p = 0; p < 4; p++) cp_part(s, kt, p);
        asm volatile("cp.async.commit_group;" ::: "memory");
    };

    const int lrow16 = lane & 15;
    const int lhi    = lane >> 4;
    auto load_afr = [&](uint32_t as_, int ks, uint32_t (*f)[4]) {
        const int chk = 2 * ks + lhi;
        #pragma unroll
        for (int mt = 0; mt < 4; mt++) {
            const int row = wm * 64 + mt * 16 + lrow16;
            ldm4(f[mt][0], f[mt][1], f[mt][2], f[mt][3],
                 as_ + row * 128 + (((row & 7) ^ chk) << 4));
        }
    };
    auto load_bfr = [&](uint32_t bs_, int ks, uint32_t (*f)[4]) {
        const int chk = 2 * ks + lhi;
        #pragma unroll
        for (int p = 0; p < 2; p++) {
            const int row = wn * 32 + p * 16 + lrow16;
            ldm4(f[p][0], f[p][1], f[p][2], f[p][3],
                 bs_ + row * 128 + (((row & 7) ^ chk) << 4));
        }
    };

    cp_stage(0, 0);
    cp_stage(1, 1);
    asm volatile("cp.async.wait_group 1;" ::: "memory");
    __syncthreads();

    float acc[4][4][4] = {};
    uint32_t af[2][4][4], bf[2][2][4];
    load_afr(sbase, 0, af[0]);
    load_bfr(sbase + 16384, 0, bf[0]);

    for (int i = 0; i < KT; i++) {
        const uint32_t as = sbase + (i % STAGES) * STAGE_BYTES;
        const uint32_t bs = as + 16384;
        const int inext = i + 2;
        const int snext = inext % STAGES;

        #pragma unroll
        for (int ks = 0; ks < 4; ks++) {
            const int cur = ks & 1, nxt = cur ^ 1;

            if (ks < 3) {
                load_afr(as, ks + 1, af[nxt]);
                load_bfr(bs, ks + 1, bf[nxt]);
            }
            if (inext < KT) cp_part(snext, inext, ks);

            if (ks == 2 && i + 1 < KT) {
                asm volatile("cp.async.wait_group 0;" ::: "memory");
                __syncthreads();
            }
            if (ks == 3) {
                if (inext < KT)
                    asm volatile("cp.async.commit_group;" ::: "memory");
                if (i + 1 < KT) {
                    const uint32_t as2 = sbase + ((i + 1) % STAGES) * STAGE_BYTES;
                    load_afr(as2, 0, af[nxt]);
                    load_bfr(as2 + 16384, 0, bf[nxt]);
                }
            }

            #pragma unroll
            for (int mt = 0; mt < 4; mt++)
                #pragma unroll
                for (int nt = 0; nt < 4; nt++)
                    mma16816(acc[mt][nt], af[cur][mt],
                             bf[cur][nt >> 1][nt & 1], bf[cur][nt >> 1][2 + (nt & 1)]);
        }
    }

    const int g   = lane >> 2;
    const int tig = lane & 3;
    const float* biasd = bias + (size_t)d * NTOT + n0 + wn * 32;
    CT* Cb = C + (size_t)(b * TT + m0 + wm * 64) * NTOT + n0 + wn * 32;

    #pragma unroll
    for (int nt = 0; nt < 4; nt++) {
        const int coff = nt * 8 + tig * 2;
        const float2 bb2 = *(const float2*)(biasd + coff);
        #pragma unroll
        for (int mt = 0; mt < 4; mt++) {
            const int r0 = mt * 16 + g;
            float2 v0, v1;
            v0.x = acc[mt][nt][0] + bb2.x;  v0.y = acc[mt][nt][1] + bb2.y;
            v1.x = acc[mt][nt][2] + bb2.x;  v1.y = acc[mt][nt][3] + bb2.y;
            if (RELU) {
                v0.x = fmaxf(v0.x, 0.0f); v0.y = fmaxf(v0.y, 0.0f);
                v1.x = fmaxf(v1.x, 0.0f); v1.y = fmaxf(v1.y, 0.0f);
            }
            if constexpr (sizeof(CT) == 2) {
                *(__half2*)((__half*)Cb + (size_t)r0 * NTOT + coff) =
                    __floats2half2_rn(v0.x, v0.y);
                *(__half2*)((__half*)Cb + (size_t)(r0 + 8) * NTOT + coff) =
                    __floats2half2_rn(v1.x, v1.y);
            } else {
                *(float2*)((float*)Cb + (size_t)r0 * NTOT + coff)       = v0;
                *(float2*)((float*)Cb + (size_t)(r0 + 8) * NTOT + coff) = v1;
            }
        }
    }
}

// ---------------------------------------------------------------- LayerNorm (= R9)
__global__ __launch_bounds__(256) void ln_kernel(
    float*       __restrict__ y,
    const float* __restrict__ gamma,
    const float* __restrict__ beta,
    const int*   __restrict__ day)
{
    const int w    = threadIdx.x >> 5;
    const int lane = threadIdx.x & 31;
    const int row0 = blockIdx.x * 16 + w * 2;
    const int b    = row0 >> 9;
    const int d    = __ldg(day + b);

    const float4* yr0 = (const float4*)(y + (size_t)row0 * DOUT);
    const float4* yr1 = (const float4*)(y + (size_t)(row0 + 1) * DOUT);

    float4 u[4], v[4];
    #pragma unroll
    for (int j = 0; j < 4; j++) u[j] = yr0[lane + 32 * j];
    #pragma unroll
    for (int j = 0; j < 4; j++) v[j] = yr1[lane + 32 * j];

    float s0 = 0.0f, q0 = 0.0f, s1 = 0.0f, q1 = 0.0f;
    #pragma unroll
    for (int j = 0; j < 4; j++) {
        s0 += u[j].x + u[j].y + u[j].z + u[j].w;
        q0 += u[j].x * u[j].x + u[j].y * u[j].y + u[j].z * u[j].z + u[j].w * u[j].w;
        s1 += v[j].x + v[j].y + v[j].z + v[j].w;
        q1 += v[j].x * v[j].x + v[j].y * v[j].y + v[j].z * v[j].z + v[j].w * v[j].w;
    }
    #pragma unroll
    for (int off = 16; off; off >>= 1) {
        s0 += __shfl_xor_sync(0xffffffffu, s0, off);
        q0 += __shfl_xor_sync(0xffffffffu, q0, off);
        s1 += __shfl_xor_sync(0xffffffffu, s1, off);
        q1 += __shfl_xor_sync(0xffffffffu, q1, off);
    }

    const float mean0 = s0 * (1.0f / DOUT);
    const float inv0  = rsqrtf(q0 * (1.0f / DOUT) - mean0 * mean0 + EPS_);
    const float mean1 = s1 * (1.0f / DOUT);
    const float inv1  = rsqrtf(q1 * (1.0f / DOUT) - mean1 * mean1 + EPS_);

    const float4* gp = (const float4*)(gamma + (size_t)d * DOUT);
    const float4* zp = (const float4*)(beta  + (size_t)d * DOUT);
    float4* yw0 = (float4*)(y + (size_t)row0 * DOUT);
    float4* yw1 = (float4*)(y + (size_t)(row0 + 1) * DOUT);

    #pragma unroll
    for (int j = 0; j < 4; j++) {
        const float4 gg = gp[lane + 32 * j];
        const float4 zz = zp[lane + 32 * j];
        float4 o0, o1;
        o0.x = (u[j].x - mean0) * inv0 * gg.x + zz.x;
        o0.y = (u[j].y - mean0) * inv0 * gg.y + zz.y;
        o0.z = (u[j].z - mean0) * inv0 * gg.z + zz.z;
        o0.w = (u[j].w - mean0) * inv0 * gg.w + zz.w;
        o1.x = (v[j].x - mean1) * inv1 * gg.x + zz.x;
        o1.y = (v[j].y - mean1) * inv1 * gg.y + zz.y;
        o1.z = (v[j].z - mean1) * inv1 * gg.z + zz.z;
        o1.w = (v[j].w - mean1) * inv1 * gg.w + zz.w;
        yw0[lane + 32 * j] = o0;
        yw1[lane + 32 * j] = o1;
    }
}

// ---------------------------------------------------------------- launch
extern "C" void kernel_launch(void* const* d_in, const int* in_sizes, int n_in,
                              void* d_out, int out_size)
{
    const float* x     = (const float*)d_in[0];
    const int*   day   = (const int*)  d_in[1];
    const float* W1    = (const float*)d_in[2];
    const float* b1    = (const float*)d_in[3];
    const float* W2    = (const float*)d_in[4];
    const float* b2    = (const float*)d_in[5];
    const float* gamma = (const float*)d_in[6];
    const float* beta  = (const float*)d_in[7];
    float* out = (float*)d_out;

    __half *xh, *h, *wt1, *wt2;
    cudaGetSymbolAddress((void**)&xh,  g_xh);
    cudaGetSymbolAddress((void**)&h,   g_h);
    cudaGetSymbolAddress((void**)&wt1, g_wt1);
    cudaGetSymbolAddress((void**)&wt2, g_wt2);

    // prep1: x convert + W1 transpose (W2 transpose fused into GEMM1's grid)
    prep1_kernel<<<NBLK_X + NBLK_W1, 256>>>((const float4*)x, (uint4*)xh, W1, wt1);

    cudaFuncSetAttribute(gemm_mma<DIN,  DHID, true,  true,  __half>,
                         cudaFuncAttributeMaxDynamicSharedMemorySize, SMEM_DYN);
    cudaFuncSetAttribute(gemm_mma<DHID, DOUT, false, false, float>,
                         cudaFuncAttributeMaxDynamicSharedMemorySize, SMEM_DYN);

    // GEMM1 (+ interleaved W2 transpose blocks): 5120 = 1024 groups of (2 gemm + 3 w2)
    gemm_mma<DIN,  DHID, true,  true,  __half><<<5120, 256, SMEM_DYN>>>(
        xh, wt1, b1, day, h, W2, wt2);
    // GEMM2: h @ W2^T -> out (wt2 completed by GEMM1 launch; stream-ordered)
    gemm_mma<DHID, DOUT, false, false, float><<<dim3(BB, TT / 128, DOUT / 128), 256, SMEM_DYN>>>(
        h, wt2, b2, day, out, nullptr, nullptr);

    ln_kernel<<<BB * TT / 16, 256>>>(out, gamma, beta, day);
}

// round 16
// speedup vs baseline: 1.0215x; 1.0215x over previous
#include <cuda_runtime.h>
#include <cuda_fp16.h>
#include <cstdint>

#define BB    64
#define TT    512
#define DIN   512
#define DHID  1024
#define DOUT  512
#define NDAYS 24
#define EPS_  1e-5f

// Scratch (__device__ globals; no runtime allocation).
__device__ __half g_xh [(size_t)BB * TT * DIN];       // 32 MB x -> fp16
__device__ __half g_h  [(size_t)BB * TT * DHID];      // 64 MB hidden fp16
__device__ __half g_wt1[(size_t)NDAYS * DHID * DIN];  // 24 MB W1^T [d][n][k] fp16
__device__ __half g_wt2[(size_t)NDAYS * DOUT * DHID]; // 24 MB W2^T [d][n][k] fp16

// ---------------------------------------------------------------- helpers
__device__ __forceinline__ uint32_t smem_u32(const void* p) {
    uint32_t a;
    asm("{ .reg .u64 t; cvta.to.shared.u64 t, %1; cvt.u32.u64 %0, t; }"
        : "=r"(a) : "l"(p));
    return a;
}
__device__ __forceinline__ void cp16(uint32_t dst, const void* src) {
    asm volatile("cp.async.cg.shared.global [%0], [%1], 16;"
                 :: "r"(dst), "l"(src) : "memory");
}
__device__ __forceinline__ void ldm4(uint32_t& r0, uint32_t& r1,
                                     uint32_t& r2, uint32_t& r3, uint32_t a) {
    asm volatile("ldmatrix.sync.aligned.m8n8.x4.shared.b16 {%0,%1,%2,%3}, [%4];"
                 : "=r"(r0), "=r"(r1), "=r"(r2), "=r"(r3) : "r"(a));
}
__device__ __forceinline__ void mma16816(float* c, const uint32_t* a,
                                         uint32_t b0, uint32_t b1) {
    asm volatile(
        "mma.sync.aligned.m16n8k16.row.col.f32.f16.f16.f32 "
        "{%0,%1,%2,%3}, {%4,%5,%6,%7}, {%8,%9}, {%0,%1,%2,%3};"
        : "+f"(c[0]), "+f"(c[1]), "+f"(c[2]), "+f"(c[3])
        : "r"(a[0]), "r"(a[1]), "r"(a[2]), "r"(a[3]), "r"(b0), "r"(b1));
}

// ---------------------------------------------------------------- fused prep
// Transpose 128(k) x 32(n) region of W [NDAYS][K][N] fp32 -> Wt [NDAYS][N][K]
// fp16.  Coarse tile: 16KB read (4 x float4/thread), 8KB write as uint4.
template<int K, int N>
__device__ __forceinline__ void transpose_tile_wide(const float* __restrict__ W,
                                                    __half* __restrict__ Wt,
                                                    int d, int n0, int k0,
                                                    float (*t)[33], int tid) {
    const float* Wd  = W  + (size_t)d * K * N;
    __half*      Wtd = Wt + (size_t)d * N * K;

    const int kr = tid >> 3;
    const int c  = (tid & 7) * 4;
    float4 v[4];
    #pragma unroll
    for (int g = 0; g < 4; g++)
        v[g] = *(const float4*)(Wd + (size_t)(k0 + g * 32 + kr) * N + n0 + c);
    #pragma unroll
    for (int g = 0; g < 4; g++) {
        const int k = g * 32 + kr;
        t[k][c + 0] = v[g].x; t[k][c + 1] = v[g].y;
        t[k][c + 2] = v[g].z; t[k][c + 3] = v[g].w;
    }
    __syncthreads();

    #pragma unroll
    for (int p = 0; p < 2; p++) {
        const int cix = p * 256 + tid;
        const int n   = cix & 31;
        const int kb  = (cix >> 5) * 8;
        __half2 h[4];
        #pragma unroll
        for (int i = 0; i < 4; i++)
            h[i] = __floats2half2_rn(t[kb + 2 * i][n], t[kb + 2 * i + 1][n]);
        uint4 o;
        o.x = *(uint32_t*)&h[0]; o.y = *(uint32_t*)&h[1];
        o.z = *(uint32_t*)&h[2]; o.w = *(uint32_t*)&h[3];
        *(uint4*)(Wtd + (size_t)(n0 + n) * K + k0 + kb) = o;
    }
}

#define NBLK_X  4096                                  // (BB*TT*DIN/16)/256
#define NBLK_W1 ((DHID / 32) * (DIN / 128) * NDAYS)   // 3072
#define NBLK_W2 ((DOUT / 32) * (DHID / 128) * NDAYS)  // 3072

__global__ __launch_bounds__(256) void prep_kernel(
    const float4* __restrict__ x, uint4* __restrict__ xh,
    const float* __restrict__ W1, __half* __restrict__ wt1,
    const float* __restrict__ W2, __half* __restrict__ wt2)
{
    __shared__ float t[128][33];
    const int blk = blockIdx.x;
    const int tid = threadIdx.x;
    if (blk < NBLK_X) {
        // 16 fp32 -> 16 fp16 per thread; loads front-batched for MLP
        const int i = blk * 256 + tid;
        float4 v[4];
        #pragma unroll
        for (int j = 0; j < 4; j++) v[j] = x[i * 4 + j];
        __half2 h[8];
        #pragma unroll
        for (int j = 0; j < 4; j++) {
            h[j * 2 + 0] = __floats2half2_rn(v[j].x, v[j].y);
            h[j * 2 + 1] = __floats2half2_rn(v[j].z, v[j].w);
        }
        uint4 o0, o1;
        o0.x = *(uint32_t*)&h[0]; o0.y = *(uint32_t*)&h[1];
        o0.z = *(uint32_t*)&h[2]; o0.w = *(uint32_t*)&h[3];
        o1.x = *(uint32_t*)&h[4]; o1.y = *(uint32_t*)&h[5];
        o1.z = *(uint32_t*)&h[6]; o1.w = *(uint32_t*)&h[7];
        xh[i * 2 + 0] = o0;
        xh[i * 2 + 1] = o1;
    } else if (blk < NBLK_X + NBLK_W1) {
        int r = blk - NBLK_X;
        const int d = r / 128; r %= 128;
        const int n0 = (r % 32) * 32;
        const int k0 = (r / 32) * 128;
        transpose_tile_wide<DIN, DHID>(W1, wt1, d, n0, k0, t, tid);
    } else {
        int r = blk - NBLK_X - NBLK_W1;
        const int d = r / 128; r %= 128;
        const int n0 = (r % 16) * 32;
        const int k0 = (r / 16) * 128;
        transpose_tile_wide<DHID, DOUT>(W2, wt2, d, n0, k0, t, tid);
    }
}

// ---------------------------------------------------------------- FP16 GEMM (= R8/R14)
// 256 threads, 8 warps 2(M) x 4(N); warp tile 64x32; K-chunk 64; 3 stages.
// Software-pipelined frags + spread cp.async; outer chunk loop ROLLED
// (full unroll blows I-cache — R9); all operands via cp.async (synchronous
// LDG in the mainloop serializes the pipeline — R13).
// Grid: x = n-tile (fastest), y = m-tile, z = b — consecutive CTAs in a
// wave share the same A tile and day weights for better L2 service latency.
#define STAGES 3
#define STAGE_BYTES 32768
#define SMEM_DYN (STAGES * STAGE_BYTES)

template<int KDIM, int NTOT, bool RELU, typename CT>
__global__ __launch_bounds__(256, 2) void gemm_mma(
    const __half* __restrict__ A,
    const __half* __restrict__ Wt,
    const float*  __restrict__ bias,
    const int*    __restrict__ day,
    CT*           __restrict__ C)
{
    extern __shared__ char smem[];
    const uint32_t sbase = smem_u32(smem);

    const int tid  = threadIdx.x;
    const int lane = tid & 31;
    const int wid  = tid >> 5;
    const int wm   = wid & 1;
    const int wn   = wid >> 1;

    const int b  = blockIdx.z;
    const int m0 = blockIdx.y * 128;
    const int n0 = blockIdx.x * 128;
    const int d  = __ldg(day + b);

    const __half* Arow = A  + (size_t)(b * TT + m0) * KDIM;
    const __half* Brow = Wt + ((size_t)d * NTOT + n0) * KDIM;

    const int lrow = tid >> 3;
    const int lchk = tid & 7;

    constexpr int KT = KDIM / 64;

    auto cp_part = [&](int s, int kt, int p) {
        const uint32_t as_ = sbase + s * STAGE_BYTES;
        const int row = p * 32 + lrow;
        const uint32_t soff = row * 128 + ((lchk ^ (row & 7)) << 4);
        const size_t goff = (size_t)kt * 64 + (size_t)row * KDIM + lchk * 8;
        cp16(as_ + soff,         Arow + goff);
        cp16(as_ + 16384 + soff, Brow + goff);
    };
    auto cp_stage = [&](int s, int kt) {
        #pragma unroll
        for (int p = 0; p < 4; p++) cp_part(s, kt, p);
        asm volatile("cp.async.commit_group;" ::: "memory");
    };

    const int lrow16 = lane & 15;
    const int lhi    = lane >> 4;
    auto load_afr = [&](uint32_t as_, int ks, uint32_t (*f)[4]) {
        const int chk = 2 * ks + lhi;
        #pragma unroll
        for (int mt = 0; mt < 4; mt++) {
            const int row = wm * 64 + mt * 16 + lrow16;
            ldm4(f[mt][0], f[mt][1], f[mt][2], f[mt][3],
                 as_ + row * 128 + (((row & 7) ^ chk) << 4));
        }
    };
    auto load_bfr = [&](uint32_t bs_, int ks, uint32_t (*f)[4]) {
        const int chk = 2 * ks + lhi;
        #pragma unroll
        for (int p = 0; p < 2; p++) {
            const int row = wn * 32 + p * 16 + lrow16;
            ldm4(f[p][0], f[p][1], f[p][2], f[p][3],
                 bs_ + row * 128 + (((row & 7) ^ chk) << 4));
        }
    };

    cp_stage(0, 0);
    cp_stage(1, 1);
    asm volatile("cp.async.wait_group 1;" ::: "memory");
    __syncthreads();

    float acc[4][4][4] = {};
    uint32_t af[2][4][4], bf[2][2][4];
    load_afr(sbase, 0, af[0]);
    load_bfr(sbase + 16384, 0, bf[0]);

    for (int i = 0; i < KT; i++) {
        const uint32_t as = sbase + (i % STAGES) * STAGE_BYTES;
        const uint32_t bs = as + 16384;
        const int inext = i + 2;
        const int snext = inext % STAGES;

        #pragma unroll
        for (int ks = 0; ks < 4; ks++) {
            const int cur = ks & 1, nxt = cur ^ 1;

            if (ks < 3) {
                load_afr(as, ks + 1, af[nxt]);
                load_bfr(bs, ks + 1, bf[nxt]);
            }
            if (inext < KT) cp_part(snext, inext, ks);

            if (ks == 2 && i + 1 < KT) {
                asm volatile("cp.async.wait_group 0;" ::: "memory");
                __syncthreads();
            }
            if (ks == 3) {
                if (inext < KT)
                    asm volatile("cp.async.commit_group;" ::: "memory");
                if (i + 1 < KT) {
                    const uint32_t as2 = sbase + ((i + 1) % STAGES) * STAGE_BYTES;
                    load_afr(as2, 0, af[nxt]);
                    load_bfr(as2 + 16384, 0, bf[nxt]);
                }
            }

            #pragma unroll
            for (int mt = 0; mt < 4; mt++)
                #pragma unroll
                for (int nt = 0; nt < 4; nt++)
                    mma16816(acc[mt][nt], af[cur][mt],
                             bf[cur][nt >> 1][nt & 1], bf[cur][nt >> 1][2 + (nt & 1)]);
        }
    }

    const int g   = lane >> 2;
    const int tig = lane & 3;
    const float* biasd = bias + (size_t)d * NTOT + n0 + wn * 32;
    CT* Cb = C + (size_t)(b * TT + m0 + wm * 64) * NTOT + n0 + wn * 32;

    #pragma unroll
    for (int nt = 0; nt < 4; nt++) {
        const int coff = nt * 8 + tig * 2;
        const float2 bb = *(const float2*)(biasd + coff);
        #pragma unroll
        for (int mt = 0; mt < 4; mt++) {
            const int r0 = mt * 16 + g;
            float2 v0, v1;
            v0.x = acc[mt][nt][0] + bb.x;  v0.y = acc[mt][nt][1] + bb.y;
            v1.x = acc[mt][nt][2] + bb.x;  v1.y = acc[mt][nt][3] + bb.y;
            if (RELU) {
                v0.x = fmaxf(v0.x, 0.0f); v0.y = fmaxf(v0.y, 0.0f);
                v1.x = fmaxf(v1.x, 0.0f); v1.y = fmaxf(v1.y, 0.0f);
            }
            if constexpr (sizeof(CT) == 2) {
                *(__half2*)((__half*)Cb + (size_t)r0 * NTOT + coff) =
                    __floats2half2_rn(v0.x, v0.y);
                *(__half2*)((__half*)Cb + (size_t)(r0 + 8) * NTOT + coff) =
                    __floats2half2_rn(v1.x, v1.y);
            } else {
                *(float2*)((float*)Cb + (size_t)r0 * NTOT + coff)       = v0;
                *(float2*)((float*)Cb + (size_t)(r0 + 8) * NTOT + coff) = v1;
            }
        }
    }
}

// ---------------------------------------------------------------- LayerNorm (= R9)
__global__ __launch_bounds__(256) void ln_kernel(
    float*       __restrict__ y,
    const float* __restrict__ gamma,
    const float* __restrict__ beta,
    const int*   __restrict__ day)
{
    const int w    = threadIdx.x >> 5;
    const int lane = threadIdx.x & 31;
    const int row0 = blockIdx.x * 16 + w * 2;
    const int b    = row0 >> 9;
    const int d    = __ldg(day + b);

    const float4* yr0 = (const float4*)(y + (size_t)row0 * DOUT);
    const float4* yr1 = (const float4*)(y + (size_t)(row0 + 1) * DOUT);

    float4 u[4], v[4];
    #pragma unroll
    for (int j = 0; j < 4; j++) u[j] = yr0[lane + 32 * j];
    #pragma unroll
    for (int j = 0; j < 4; j++) v[j] = yr1[lane + 32 * j];

    float s0 = 0.0f, q0 = 0.0f, s1 = 0.0f, q1 = 0.0f;
    #pragma unroll
    for (int j = 0; j < 4; j++) {
        s0 += u[j].x + u[j].y + u[j].z + u[j].w;
        q0 += u[j].x * u[j].x + u[j].y * u[j].y + u[j].z * u[j].z + u[j].w * u[j].w;
        s1 += v[j].x + v[j].y + v[j].z + v[j].w;
        q1 += v[j].x * v[j].x + v[j].y * v[j].y + v[j].z * v[j].z + v[j].w * v[j].w;
    }
    #pragma unroll
    for (int off = 16; off; off >>= 1) {
        s0 += __shfl_xor_sync(0xffffffffu, s0, off);
        q0 += __shfl_xor_sync(0xffffffffu, q0, off);
        s1 += __shfl_xor_sync(0xffffffffu, s1, off);
        q1 += __shfl_xor_sync(0xffffffffu, q1, off);
    }

    const float mean0 = s0 * (1.0f / DOUT);
    const float inv0  = rsqrtf(q0 * (1.0f / DOUT) - mean0 * mean0 + EPS_);
    const float mean1 = s1 * (1.0f / DOUT);
    const float inv1  = rsqrtf(q1 * (1.0f / DOUT) - mean1 * mean1 + EPS_);

    const float4* gp = (const float4*)(gamma + (size_t)d * DOUT);
    const float4* zp = (const float4*)(beta  + (size_t)d * DOUT);
    float4* yw0 = (float4*)(y + (size_t)row0 * DOUT);
    float4* yw1 = (float4*)(y + (size_t)(row0 + 1) * DOUT);

    #pragma unroll
    for (int j = 0; j < 4; j++) {
        const float4 gg = gp[lane + 32 * j];
        const float4 zz = zp[lane + 32 * j];
        float4 o0, o1;
        o0.x = (u[j].x - mean0) * inv0 * gg.x + zz.x;
        o0.y = (u[j].y - mean0) * inv0 * gg.y + zz.y;
        o0.z = (u[j].z - mean0) * inv0 * gg.z + zz.z;
        o0.w = (u[j].w - mean0) * inv0 * gg.w + zz.w;
        o1.x = (v[j].x - mean1) * inv1 * gg.x + zz.x;
        o1.y = (v[j].y - mean1) * inv1 * gg.y + zz.y;
        o1.z = (v[j].z - mean1) * inv1 * gg.z + zz.z;
        o1.w = (v[j].w - mean1) * inv1 * gg.w + zz.w;
        yw0[lane + 32 * j] = o0;
        yw1[lane + 32 * j] = o1;
    }
}

// ---------------------------------------------------------------- launch
extern "C" void kernel_launch(void* const* d_in, const int* in_sizes, int n_in,
                              void* d_out, int out_size)
{
    const float* x     = (const float*)d_in[0];
    const int*   day   = (const int*)  d_in[1];
    const float* W1    = (const float*)d_in[2];
    const float* b1    = (const float*)d_in[3];
    const float* W2    = (const float*)d_in[4];
    const float* b2    = (const float*)d_in[5];
    const float* gamma = (const float*)d_in[6];
    const float* beta  = (const float*)d_in[7];
    float* out = (float*)d_out;

    __half *xh, *h, *wt1, *wt2;
    cudaGetSymbolAddress((void**)&xh,  g_xh);
    cudaGetSymbolAddress((void**)&h,   g_h);
    cudaGetSymbolAddress((void**)&wt1, g_wt1);
    cudaGetSymbolAddress((void**)&wt2, g_wt2);

    prep_kernel<<<NBLK_X + NBLK_W1 + NBLK_W2, 256>>>(
        (const float4*)x, (uint4*)xh, W1, wt1, W2, wt2);

    cudaFuncSetAttribute(gemm_mma<DIN,  DHID, true,  __half>,
                         cudaFuncAttributeMaxDynamicSharedMemorySize, SMEM_DYN);
    cudaFuncSetAttribute(gemm_mma<DHID, DOUT, false, float>,
                         cudaFuncAttributeMaxDynamicSharedMemorySize, SMEM_DYN);

    // grid: x = n-tile (fastest) for A-tile / day-weight L2 sharing
    gemm_mma<DIN,  DHID, true,  __half><<<dim3(DHID / 128, TT / 128, BB), 256, SMEM_DYN>>>(
        xh, wt1, b1, day, h);
    gemm_mma<DHID, DOUT, false, float><<<dim3(DOUT / 128, TT / 128, BB), 256, SMEM_DYN>>>(
        h, wt2, b2, day, out);

    ln_kernel<<<BB * TT / 16, 256>>>(out, gamma, beta, day);
}